// round 1
// baseline (speedup 1.0000x reference)
#include <cuda_runtime.h>
#include <math.h>

#define Bk 2
#define Sk 2048
#define Dk 1024
#define Hk 16
#define HDk 64
#define NEG_INF -9.0e15f

// Scratch (allocation-free rule: __device__ globals)
__device__ float g_Q[Bk*Hk*Sk*HDk];
__device__ float g_K[Bk*Hk*Sk*HDk];
__device__ float g_V[Bk*Hk*Sk*HDk];
__device__ float g_ctx[Bk*Sk*Dk];

// ---------------------------------------------------------------------------
// NT GEMM: C[m,n] = sum_k A[m,k] * B[n,k] + bias[n]
// MODE 0: A = x, B = w_qkv, scatter epilogue into g_Q/g_K/g_V
// MODE 1: A = g_ctx (param ignored), B = w_o, write Cout (d_out)
// 128x128 tile, BK=8, 256 threads, 8x8 per thread (split 4+4 halves).
// ---------------------------------------------------------------------------
template<int MODE>
__global__ __launch_bounds__(256) void gemm128(
    const float* __restrict__ A, const float* __restrict__ Bw,
    const float* __restrict__ bias, float* __restrict__ Cout,
    int M, int N, int K)
{
    __shared__ float As[8][128];
    __shared__ float Bs[8][128];
    const int tid = threadIdx.x;
    const int tx = tid & 15, ty = tid >> 4;
    const int m0 = blockIdx.y * 128, n0 = blockIdx.x * 128;
    const int lrow = tid >> 1;        // 0..127
    const int lk   = (tid & 1) * 4;   // 0 or 4

    const float* Abase = (MODE == 1) ? g_ctx : A;
    const float* Aptr = Abase + (size_t)(m0 + lrow) * K + lk;
    const float* Bptr = Bw    + (size_t)(n0 + lrow) * K + lk;

    float4 aR = *(const float4*)Aptr;
    float4 bR = *(const float4*)Bptr;

    float acc[8][8];
#pragma unroll
    for (int i = 0; i < 8; i++)
#pragma unroll
        for (int j = 0; j < 8; j++) acc[i][j] = 0.f;

    for (int kt = 0; kt < K; kt += 8) {
        As[lk+0][lrow] = aR.x; As[lk+1][lrow] = aR.y;
        As[lk+2][lrow] = aR.z; As[lk+3][lrow] = aR.w;
        Bs[lk+0][lrow] = bR.x; Bs[lk+1][lrow] = bR.y;
        Bs[lk+2][lrow] = bR.z; Bs[lk+3][lrow] = bR.w;
        __syncthreads();
        if (kt + 8 < K) {   // prefetch next tile while computing
            aR = *(const float4*)(Aptr + kt + 8);
            bR = *(const float4*)(Bptr + kt + 8);
        }
#pragma unroll
        for (int k = 0; k < 8; k++) {
            float4 a0 = *(const float4*)&As[k][ty * 4];
            float4 a1 = *(const float4*)&As[k][64 + ty * 4];
            float4 b0 = *(const float4*)&Bs[k][tx * 4];
            float4 b1 = *(const float4*)&Bs[k][64 + tx * 4];
            float av[8] = {a0.x,a0.y,a0.z,a0.w,a1.x,a1.y,a1.z,a1.w};
            float bv[8] = {b0.x,b0.y,b0.z,b0.w,b1.x,b1.y,b1.z,b1.w};
#pragma unroll
            for (int i = 0; i < 8; i++)
#pragma unroll
                for (int j = 0; j < 8; j++)
                    acc[i][j] = fmaf(av[i], bv[j], acc[i][j]);
        }
        __syncthreads();
    }

#pragma unroll
    for (int i = 0; i < 8; i++) {
        int m = m0 + ((i < 4) ? (ty * 4 + i) : (64 + ty * 4 + i - 4));
#pragma unroll
        for (int j = 0; j < 8; j++) {
            int n = n0 + ((j < 4) ? (tx * 4 + j) : (64 + tx * 4 + j - 4));
            float v = acc[i][j] + __ldg(&bias[n]);
            if (MODE == 0) {
                // qkv[m, n] -> n = h*192 + t; t<64:Q, t<128:K, else V
                int b = m >> 11, s = m & (Sk - 1);
                int h = n / 192, t = n - h * 192;
                int sel = t >> 6, d = t & 63;
                float* dst = (sel == 0) ? g_Q : ((sel == 1) ? g_K : g_V);
                dst[((size_t)((b << 4) + h) * Sk + s) * HDk + d] = v;
            } else {
                Cout[(size_t)m * N + n] = v;
            }
        }
    }
}

// ---------------------------------------------------------------------------
// Flash attention: one block = 64 queries x (loop over 64-key tiles), hd=64.
// 256 threads as 16x16; thread owns rows q0+ty+16*ii, cols tx+16*jj.
// ---------------------------------------------------------------------------
__device__ __forceinline__ float redmax16(float v) {
    v = fmaxf(v, __shfl_xor_sync(0xffffffffu, v, 1));
    v = fmaxf(v, __shfl_xor_sync(0xffffffffu, v, 2));
    v = fmaxf(v, __shfl_xor_sync(0xffffffffu, v, 4));
    v = fmaxf(v, __shfl_xor_sync(0xffffffffu, v, 8));
    return v;
}
__device__ __forceinline__ float redsum16(float v) {
    v += __shfl_xor_sync(0xffffffffu, v, 1);
    v += __shfl_xor_sync(0xffffffffu, v, 2);
    v += __shfl_xor_sync(0xffffffffu, v, 4);
    v += __shfl_xor_sync(0xffffffffu, v, 8);
    return v;
}

#define QS 64
#define KS 65   // pad -> conflict-free Ks[(tx+16jj)*65 + d] reads
#define VS 64
#define PS 64

__global__ __launch_bounds__(256, 3) void flash_attn(const int* __restrict__ mask)
{
    extern __shared__ float sm[];
    float* Qs = sm;             // 64*QS
    float* Ks = Qs + 64 * QS;   // 64*KS
    float* Vs = Ks + 64 * KS;   // 64*VS
    float* Ps = Vs + 64 * VS;   // 64*PS

    const int tid = threadIdx.x;
    const int tx = tid & 15, ty = tid >> 4;
    const int bh = blockIdx.y;
    const int q0 = blockIdx.x * 64;
    const float* Qg = g_Q + (size_t)bh * Sk * HDk;
    const float* Kg = g_K + (size_t)bh * Sk * HDk;
    const float* Vg = g_V + (size_t)bh * Sk * HDk;

    // Load Q tile, pre-scaled by 1/sqrt(hd) = 0.125
#pragma unroll
    for (int it = 0; it < 4; it++) {
        int idx = it * 256 + tid;
        int s = idx >> 4, d4 = (idx & 15) * 4;
        float4 v = *(const float4*)(Qg + (size_t)(q0 + s) * HDk + d4);
        v.x *= 0.125f; v.y *= 0.125f; v.z *= 0.125f; v.w *= 0.125f;
        *(float4*)&Qs[s * QS + d4] = v;
    }

    float o[4][4];
    float mrow[4], lrow[4];
#pragma unroll
    for (int ii = 0; ii < 4; ii++) {
        mrow[ii] = -INFINITY; lrow[ii] = 0.f;
#pragma unroll
        for (int jj = 0; jj < 4; jj++) o[ii][jj] = 0.f;
    }
    __syncthreads();

    for (int kt = 0; kt < Sk; kt += 64) {
        // Load K, V tiles
#pragma unroll
        for (int it = 0; it < 4; it++) {
            int idx = it * 256 + tid;
            int s = idx >> 4, d4 = (idx & 15) * 4;
            float4 kv = *(const float4*)(Kg + (size_t)(kt + s) * HDk + d4);
            Ks[s * KS + d4 + 0] = kv.x;
            Ks[s * KS + d4 + 1] = kv.y;
            Ks[s * KS + d4 + 2] = kv.z;
            Ks[s * KS + d4 + 3] = kv.w;
            float4 vv = *(const float4*)(Vg + (size_t)(kt + s) * HDk + d4);
            *(float4*)&Vs[s * VS + d4] = vv;
        }
        __syncthreads();

        // S = Q K^T (Q pre-scaled)
        float sc[4][4];
#pragma unroll
        for (int ii = 0; ii < 4; ii++)
#pragma unroll
            for (int jj = 0; jj < 4; jj++) sc[ii][jj] = 0.f;
#pragma unroll 16
        for (int d = 0; d < 64; d++) {
            float a[4], bb[4];
#pragma unroll
            for (int ii = 0; ii < 4; ii++) a[ii] = Qs[(ty + 16 * ii) * QS + d];
#pragma unroll
            for (int jj = 0; jj < 4; jj++) bb[jj] = Ks[(tx + 16 * jj) * KS + d];
#pragma unroll
            for (int ii = 0; ii < 4; ii++)
#pragma unroll
                for (int jj = 0; jj < 4; jj++)
                    sc[ii][jj] = fmaf(a[ii], bb[jj], sc[ii][jj]);
        }

        // Mask (mask==0 -> NEG_INF, matching reference semantics exactly)
#pragma unroll
        for (int ii = 0; ii < 4; ii++)
#pragma unroll
            for (int jj = 0; jj < 4; jj++) {
                int mval = __ldg(&mask[(size_t)(q0 + ty + 16 * ii) * Sk + kt + tx + 16 * jj]);
                sc[ii][jj] = mval ? sc[ii][jj] : NEG_INF;
            }

        // Online softmax update
#pragma unroll
        for (int ii = 0; ii < 4; ii++) {
            float tmax = fmaxf(fmaxf(sc[ii][0], sc[ii][1]), fmaxf(sc[ii][2], sc[ii][3]));
            tmax = redmax16(tmax);
            float mnew = fmaxf(mrow[ii], tmax);
            float corr = __expf(mrow[ii] - mnew);
            mrow[ii] = mnew;
            float rs = 0.f;
#pragma unroll
            for (int jj = 0; jj < 4; jj++) {
                float p = __expf(sc[ii][jj] - mnew);
                sc[ii][jj] = p;
                rs += p;
            }
            rs = redsum16(rs);
            lrow[ii] = lrow[ii] * corr + rs;
#pragma unroll
            for (int jj = 0; jj < 4; jj++) o[ii][jj] *= corr;
        }

        // P -> smem
#pragma unroll
        for (int ii = 0; ii < 4; ii++)
#pragma unroll
            for (int jj = 0; jj < 4; jj++)
                Ps[(ty + 16 * ii) * PS + tx + 16 * jj] = sc[ii][jj];
        __syncthreads();

        // O += P @ V
#pragma unroll 16
        for (int kk = 0; kk < 64; kk++) {
            float a[4], bb[4];
#pragma unroll
            for (int ii = 0; ii < 4; ii++) a[ii] = Ps[(ty + 16 * ii) * PS + kk];
#pragma unroll
            for (int jj = 0; jj < 4; jj++) bb[jj] = Vs[kk * VS + tx + 16 * jj];
#pragma unroll
            for (int ii = 0; ii < 4; ii++)
#pragma unroll
                for (int jj = 0; jj < 4; jj++)
                    o[ii][jj] = fmaf(a[ii], bb[jj], o[ii][jj]);
        }
        __syncthreads();
    }

    // Epilogue: ctx[b, q, h*64 + c] = o / l
    const int b = bh >> 4, h = bh & 15;
#pragma unroll
    for (int ii = 0; ii < 4; ii++) {
        float inv = 1.f / lrow[ii];
        int q = q0 + ty + 16 * ii;
#pragma unroll
        for (int jj = 0; jj < 4; jj++) {
            int c = tx + 16 * jj;
            g_ctx[(size_t)(b * Sk + q) * Dk + h * HDk + c] = o[ii][jj] * inv;
        }
    }
}

// ---------------------------------------------------------------------------
extern "C" void kernel_launch(void* const* d_in, const int* in_sizes, int n_in,
                              void* d_out, int out_size)
{
    const float* x     = (const float*)d_in[0];
    const int*   mask  = (const int*)  d_in[1];
    const float* w_qkv = (const float*)d_in[2];
    const float* b_qkv = (const float*)d_in[3];
    const float* w_o   = (const float*)d_in[4];
    const float* b_o   = (const float*)d_in[5];
    float* out = (float*)d_out;

    // 1) QKV projection + head scatter
    gemm128<0><<<dim3((3 * Dk) / 128, (Bk * Sk) / 128), 256>>>(
        x, w_qkv, b_qkv, nullptr, Bk * Sk, 3 * Dk, Dk);

    // 2) Flash attention
    const int smem = (64 * QS + 64 * KS + 64 * VS + 64 * PS) * (int)sizeof(float);
    cudaFuncSetAttribute(flash_attn, cudaFuncAttributeMaxDynamicSharedMemorySize, smem);
    flash_attn<<<dim3(Sk / 64, Bk * Hk), 256, smem>>>(mask);

    // 3) Output projection
    gemm128<1><<<dim3(Dk / 128, (Bk * Sk) / 128), 256>>>(
        x /*ignored*/, w_o, b_o, out, Bk * Sk, Dk, Dk);
}

// round 2
// speedup vs baseline: 1.2362x; 1.2362x over previous
#include <cuda_runtime.h>
#include <math.h>
#include <stdint.h>

#define Bk 2
#define Sk 2048
#define Dk 1024
#define Hk 16
#define HDk 64
#define NEG_INF -9.0e15f

// Scratch (allocation-free rule: __device__ globals)
__device__ float g_Q[Bk*Hk*Sk*HDk];
__device__ float g_K[Bk*Hk*Sk*HDk];
__device__ float g_V[Bk*Hk*Sk*HDk];
__device__ float g_ctx[Bk*Sk*Dk];

__device__ __forceinline__ uint32_t f2tf32(float f) {
    uint32_t u;
    asm("cvt.rna.tf32.f32 %0, %1;" : "=r"(u) : "f"(f));
    return u;
}

__device__ __forceinline__ void mma_tf32(float c[4], const uint32_t a[4], const uint32_t b[2]) {
    asm volatile(
        "mma.sync.aligned.m16n8k8.row.col.f32.tf32.tf32.f32 "
        "{%0,%1,%2,%3},{%4,%5,%6,%7},{%8,%9},{%0,%1,%2,%3};"
        : "+f"(c[0]), "+f"(c[1]), "+f"(c[2]), "+f"(c[3])
        : "r"(a[0]), "r"(a[1]), "r"(a[2]), "r"(a[3]), "r"(b[0]), "r"(b[1]));
}

// ---------------------------------------------------------------------------
// TF32 tensor-core NT GEMM: C[m,n] = sum_k A[m,k]*B[n,k] + bias[n]
// Block tile 128x128, BK=32 (double-buffered), 8 warps of 64x32.
// MODE 0: A = x, B = w_qkv, scatter into g_Q/g_K/g_V
// MODE 1: A = g_ctx, B = w_o, write Cout
// Smem layout [row][k] stride 36 words -> conflict-free fragment LDS.
// ---------------------------------------------------------------------------
#define SSTR 36
#define TBUF (128 * SSTR)

template<int MODE>
__global__ __launch_bounds__(256) void gemm_tc(
    const float* __restrict__ A, const float* __restrict__ Bw,
    const float* __restrict__ bias, float* __restrict__ Cout,
    int M, int N, int K)
{
    extern __shared__ uint32_t sh[];
    uint32_t* As = sh;              // [2][128][36]
    uint32_t* Bs = sh + 2 * TBUF;   // [2][128][36]

    const int tid = threadIdx.x;
    const int wid = tid >> 5, lane = tid & 31;
    const int g = lane >> 2, t = lane & 3;
    const int wm = wid >> 2, wn = wid & 3;
    const int m0 = blockIdx.y * 128, n0 = blockIdx.x * 128;

    const float* Abase = (MODE == 1) ? g_ctx : A;

    const int lrow = tid >> 1;        // 0..127
    const int lq   = (tid & 1) * 16;  // 0 or 16

    const float* Ap = Abase + (size_t)(m0 + lrow) * K + lq;
    const float* Bp = Bw    + (size_t)(n0 + lrow) * K + lq;

    float4 ra[4], rb[4];
#pragma unroll
    for (int j = 0; j < 4; j++) {
        ra[j] = *(const float4*)(Ap + 4 * j);
        rb[j] = *(const float4*)(Bp + 4 * j);
    }

    float acc[4][4][4];
#pragma unroll
    for (int mi = 0; mi < 4; mi++)
#pragma unroll
        for (int ni = 0; ni < 4; ni++)
#pragma unroll
            for (int e = 0; e < 4; e++) acc[mi][ni][e] = 0.f;

    const int stBase = lrow * SSTR + lq;
    const int aBase = (wm * 64 + g) * SSTR + t;
    const int bBase = (wn * 32 + g) * SSTR + t;
    const int NT = K >> 5;

    // stage tile 0
#pragma unroll
    for (int j = 0; j < 4; j++) {
        uint32_t* a = As + stBase + 4 * j;
        a[0] = f2tf32(ra[j].x); a[1] = f2tf32(ra[j].y);
        a[2] = f2tf32(ra[j].z); a[3] = f2tf32(ra[j].w);
        uint32_t* b = Bs + stBase + 4 * j;
        b[0] = f2tf32(rb[j].x); b[1] = f2tf32(rb[j].y);
        b[2] = f2tf32(rb[j].z); b[3] = f2tf32(rb[j].w);
    }
    __syncthreads();

    for (int kt = 0; kt < NT; kt++) {
        if (kt + 1 < NT) {
            Ap += 32; Bp += 32;
#pragma unroll
            for (int j = 0; j < 4; j++) {
                ra[j] = *(const float4*)(Ap + 4 * j);
                rb[j] = *(const float4*)(Bp + 4 * j);
            }
        }
        const uint32_t* a = As + (kt & 1) * TBUF;
        const uint32_t* b = Bs + (kt & 1) * TBUF;
#pragma unroll
        for (int kc = 0; kc < 32; kc += 8) {
            uint32_t af[4][4], bf[4][2];
#pragma unroll
            for (int mi = 0; mi < 4; mi++) {
                int base = aBase + mi * 16 * SSTR + kc;
                af[mi][0] = a[base];
                af[mi][1] = a[base + 8 * SSTR];
                af[mi][2] = a[base + 4];
                af[mi][3] = a[base + 8 * SSTR + 4];
            }
#pragma unroll
            for (int ni = 0; ni < 4; ni++) {
                int base = bBase + ni * 8 * SSTR + kc;
                bf[ni][0] = b[base];
                bf[ni][1] = b[base + 4];
            }
#pragma unroll
            for (int mi = 0; mi < 4; mi++)
#pragma unroll
                for (int ni = 0; ni < 4; ni++)
                    mma_tf32(acc[mi][ni], af[mi], bf[ni]);
        }
        if (kt + 1 < NT) {
            uint32_t* an = As + ((kt + 1) & 1) * TBUF + stBase;
            uint32_t* bn = Bs + ((kt + 1) & 1) * TBUF + stBase;
#pragma unroll
            for (int j = 0; j < 4; j++) {
                an[4*j+0] = f2tf32(ra[j].x); an[4*j+1] = f2tf32(ra[j].y);
                an[4*j+2] = f2tf32(ra[j].z); an[4*j+3] = f2tf32(ra[j].w);
                bn[4*j+0] = f2tf32(rb[j].x); bn[4*j+1] = f2tf32(rb[j].y);
                bn[4*j+2] = f2tf32(rb[j].z); bn[4*j+3] = f2tf32(rb[j].w);
            }
            __syncthreads();
        }
    }

    // Epilogue
#pragma unroll
    for (int mi = 0; mi < 4; mi++) {
        int r0 = m0 + wm * 64 + mi * 16 + g;
#pragma unroll
        for (int ni = 0; ni < 4; ni++) {
            int c0 = n0 + wn * 32 + ni * 8 + 2 * t;
#pragma unroll
            for (int e = 0; e < 4; e++) {
                int m = r0 + (e >> 1) * 8;
                int n = c0 + (e & 1);
                float v = acc[mi][ni][e] + __ldg(&bias[n]);
                if (MODE == 0) {
                    int b_ = m >> 11, s = m & (Sk - 1);
                    int h = n / 192, tt = n - h * 192;
                    int sel = tt >> 6, d = tt & 63;
                    float* dst = (sel == 0) ? g_Q : ((sel == 1) ? g_K : g_V);
                    dst[((size_t)((b_ << 4) + h) * Sk + s) * HDk + d] = v;
                } else {
                    Cout[(size_t)m * N + n] = v;
                }
            }
        }
    }
}

// ---------------------------------------------------------------------------
// Flash attention (unchanged math from round 1; mask loads hoisted)
// ---------------------------------------------------------------------------
__device__ __forceinline__ float redmax16(float v) {
    v = fmaxf(v, __shfl_xor_sync(0xffffffffu, v, 1));
    v = fmaxf(v, __shfl_xor_sync(0xffffffffu, v, 2));
    v = fmaxf(v, __shfl_xor_sync(0xffffffffu, v, 4));
    v = fmaxf(v, __shfl_xor_sync(0xffffffffu, v, 8));
    return v;
}
__device__ __forceinline__ float redsum16(float v) {
    v += __shfl_xor_sync(0xffffffffu, v, 1);
    v += __shfl_xor_sync(0xffffffffu, v, 2);
    v += __shfl_xor_sync(0xffffffffu, v, 4);
    v += __shfl_xor_sync(0xffffffffu, v, 8);
    return v;
}

#define QS 64
#define KS 65
#define VS 64
#define PS 64

__global__ __launch_bounds__(256, 3) void flash_attn(const int* __restrict__ mask)
{
    extern __shared__ float sm[];
    float* Qs = sm;
    float* Ks = Qs + 64 * QS;
    float* Vs = Ks + 64 * KS;
    float* Ps = Vs + 64 * VS;

    const int tid = threadIdx.x;
    const int tx = tid & 15, ty = tid >> 4;
    const int bh = blockIdx.y;
    const int q0 = blockIdx.x * 64;
    const float* Qg = g_Q + (size_t)bh * Sk * HDk;
    const float* Kg = g_K + (size_t)bh * Sk * HDk;
    const float* Vg = g_V + (size_t)bh * Sk * HDk;

#pragma unroll
    for (int it = 0; it < 4; it++) {
        int idx = it * 256 + tid;
        int s = idx >> 4, d4 = (idx & 15) * 4;
        float4 v = *(const float4*)(Qg + (size_t)(q0 + s) * HDk + d4);
        v.x *= 0.125f; v.y *= 0.125f; v.z *= 0.125f; v.w *= 0.125f;
        *(float4*)&Qs[s * QS + d4] = v;
    }

    float o[4][4];
    float mrow[4], lrow[4];
#pragma unroll
    for (int ii = 0; ii < 4; ii++) {
        mrow[ii] = -INFINITY; lrow[ii] = 0.f;
#pragma unroll
        for (int jj = 0; jj < 4; jj++) o[ii][jj] = 0.f;
    }
    __syncthreads();

    for (int kt = 0; kt < Sk; kt += 64) {
#pragma unroll
        for (int it = 0; it < 4; it++) {
            int idx = it * 256 + tid;
            int s = idx >> 4, d4 = (idx & 15) * 4;
            float4 kv = *(const float4*)(Kg + (size_t)(kt + s) * HDk + d4);
            Ks[s * KS + d4 + 0] = kv.x;
            Ks[s * KS + d4 + 1] = kv.y;
            Ks[s * KS + d4 + 2] = kv.z;
            Ks[s * KS + d4 + 3] = kv.w;
            float4 vv = *(const float4*)(Vg + (size_t)(kt + s) * HDk + d4);
            *(float4*)&Vs[s * VS + d4] = vv;
        }

        // hoisted mask loads (overlap with K/V smem fill + QK compute)
        int mv[4][4];
#pragma unroll
        for (int ii = 0; ii < 4; ii++)
#pragma unroll
            for (int jj = 0; jj < 4; jj++)
                mv[ii][jj] = __ldg(&mask[(size_t)(q0 + ty + 16 * ii) * Sk + kt + tx + 16 * jj]);
        __syncthreads();

        float sc[4][4];
#pragma unroll
        for (int ii = 0; ii < 4; ii++)
#pragma unroll
            for (int jj = 0; jj < 4; jj++) sc[ii][jj] = 0.f;
#pragma unroll 16
        for (int d = 0; d < 64; d++) {
            float a[4], bb[4];
#pragma unroll
            for (int ii = 0; ii < 4; ii++) a[ii] = Qs[(ty + 16 * ii) * QS + d];
#pragma unroll
            for (int jj = 0; jj < 4; jj++) bb[jj] = Ks[(tx + 16 * jj) * KS + d];
#pragma unroll
            for (int ii = 0; ii < 4; ii++)
#pragma unroll
                for (int jj = 0; jj < 4; jj++)
                    sc[ii][jj] = fmaf(a[ii], bb[jj], sc[ii][jj]);
        }

#pragma unroll
        for (int ii = 0; ii < 4; ii++)
#pragma unroll
            for (int jj = 0; jj < 4; jj++)
                sc[ii][jj] = mv[ii][jj] ? sc[ii][jj] : NEG_INF;

#pragma unroll
        for (int ii = 0; ii < 4; ii++) {
            float tmax = fmaxf(fmaxf(sc[ii][0], sc[ii][1]), fmaxf(sc[ii][2], sc[ii][3]));
            tmax = redmax16(tmax);
            float mnew = fmaxf(mrow[ii], tmax);
            float corr = __expf(mrow[ii] - mnew);
            mrow[ii] = mnew;
            float rs = 0.f;
#pragma unroll
            for (int jj = 0; jj < 4; jj++) {
                float p = __expf(sc[ii][jj] - mnew);
                sc[ii][jj] = p;
                rs += p;
            }
            rs = redsum16(rs);
            lrow[ii] = lrow[ii] * corr + rs;
#pragma unroll
            for (int jj = 0; jj < 4; jj++) o[ii][jj] *= corr;
        }

#pragma unroll
        for (int ii = 0; ii < 4; ii++)
#pragma unroll
            for (int jj = 0; jj < 4; jj++)
                Ps[(ty + 16 * ii) * PS + tx + 16 * jj] = sc[ii][jj];
        __syncthreads();

#pragma unroll 16
        for (int kk = 0; kk < 64; kk++) {
            float a[4], bb[4];
#pragma unroll
            for (int ii = 0; ii < 4; ii++) a[ii] = Ps[(ty + 16 * ii) * PS + kk];
#pragma unroll
            for (int jj = 0; jj < 4; jj++) bb[jj] = Vs[kk * VS + tx + 16 * jj];
#pragma unroll
            for (int ii = 0; ii < 4; ii++)
#pragma unroll
                for (int jj = 0; jj < 4; jj++)
                    o[ii][jj] = fmaf(a[ii], bb[jj], o[ii][jj]);
        }
        __syncthreads();
    }

    const int b = bh >> 4, h = bh & 15;
#pragma unroll
    for (int ii = 0; ii < 4; ii++) {
        float inv = 1.f / lrow[ii];
        int q = q0 + ty + 16 * ii;
#pragma unroll
        for (int jj = 0; jj < 4; jj++) {
            int c = tx + 16 * jj;
            g_ctx[(size_t)(b * Sk + q) * Dk + h * HDk + c] = o[ii][jj] * inv;
        }
    }
}

// ---------------------------------------------------------------------------
extern "C" void kernel_launch(void* const* d_in, const int* in_sizes, int n_in,
                              void* d_out, int out_size)
{
    const float* x     = (const float*)d_in[0];
    const int*   mask  = (const int*)  d_in[1];
    const float* w_qkv = (const float*)d_in[2];
    const float* b_qkv = (const float*)d_in[3];
    const float* w_o   = (const float*)d_in[4];
    const float* b_o   = (const float*)d_in[5];
    float* out = (float*)d_out;

    const int gsmem = 4 * TBUF * (int)sizeof(uint32_t);  // 73728 B
    cudaFuncSetAttribute(gemm_tc<0>, cudaFuncAttributeMaxDynamicSharedMemorySize, gsmem);
    cudaFuncSetAttribute(gemm_tc<1>, cudaFuncAttributeMaxDynamicSharedMemorySize, gsmem);

    // 1) QKV projection + head scatter (tensor cores, TF32)
    gemm_tc<0><<<dim3((3 * Dk) / 128, (Bk * Sk) / 128), 256, gsmem>>>(
        x, w_qkv, b_qkv, nullptr, Bk * Sk, 3 * Dk, Dk);

    // 2) Flash attention
    const int fsmem = (64 * QS + 64 * KS + 64 * VS + 64 * PS) * (int)sizeof(float);
    cudaFuncSetAttribute(flash_attn, cudaFuncAttributeMaxDynamicSharedMemorySize, fsmem);
    flash_attn<<<dim3(Sk / 64, Bk * Hk), 256, fsmem>>>(mask);

    // 3) Output projection (tensor cores, TF32)
    gemm_tc<1><<<dim3(Dk / 128, (Bk * Sk) / 128), 256, gsmem>>>(
        x /*ignored*/, w_o, b_o, out, Bk * Sk, Dk, Dk);
}

// round 3
// speedup vs baseline: 1.8153x; 1.4685x over previous
#include <cuda_runtime.h>
#include <cuda_fp16.h>
#include <math.h>
#include <stdint.h>

#define Bk 2
#define Sk 2048
#define Dk 1024
#define Hk 16
#define HDk 64
#define NEG_INF -9.0e15f

// Scratch (allocation-free rule: __device__ globals)
__device__ float g_Q[Bk*Hk*Sk*HDk];
__device__ float g_K[Bk*Hk*Sk*HDk];
__device__ float g_V[Bk*Hk*Sk*HDk];
__device__ float g_ctx[Bk*Sk*Dk];
__device__ uint32_t g_mbits[Sk * (Sk / 32)];

__device__ __forceinline__ uint32_t f2tf32(float f) {
    uint32_t u;
    asm("cvt.rna.tf32.f32 %0, %1;" : "=r"(u) : "f"(f));
    return u;
}

__device__ __forceinline__ void mma_tf32(float c[4], const uint32_t a[4], const uint32_t b[2]) {
    asm volatile(
        "mma.sync.aligned.m16n8k8.row.col.f32.tf32.tf32.f32 "
        "{%0,%1,%2,%3},{%4,%5,%6,%7},{%8,%9},{%0,%1,%2,%3};"
        : "+f"(c[0]), "+f"(c[1]), "+f"(c[2]), "+f"(c[3])
        : "r"(a[0]), "r"(a[1]), "r"(a[2]), "r"(a[3]), "r"(b[0]), "r"(b[1]));
}

__device__ __forceinline__ void mma_f16(float c[4], const uint32_t a[4], const uint32_t b[2]) {
    asm volatile(
        "mma.sync.aligned.m16n8k16.row.col.f32.f16.f16.f32 "
        "{%0,%1,%2,%3},{%4,%5,%6,%7},{%8,%9},{%0,%1,%2,%3};"
        : "+f"(c[0]), "+f"(c[1]), "+f"(c[2]), "+f"(c[3])
        : "r"(a[0]), "r"(a[1]), "r"(a[2]), "r"(a[3]), "r"(b[0]), "r"(b[1]));
}

// ---------------------------------------------------------------------------
// TF32 tensor-core NT GEMM (unchanged from round 2)
// ---------------------------------------------------------------------------
#define SSTR 36
#define TBUF (128 * SSTR)

template<int MODE>
__global__ __launch_bounds__(256) void gemm_tc(
    const float* __restrict__ A, const float* __restrict__ Bw,
    const float* __restrict__ bias, float* __restrict__ Cout,
    int M, int N, int K)
{
    extern __shared__ uint32_t sh[];
    uint32_t* As = sh;
    uint32_t* Bs = sh + 2 * TBUF;

    const int tid = threadIdx.x;
    const int wid = tid >> 5, lane = tid & 31;
    const int g = lane >> 2, t = lane & 3;
    const int wm = wid >> 2, wn = wid & 3;
    const int m0 = blockIdx.y * 128, n0 = blockIdx.x * 128;

    const float* Abase = (MODE == 1) ? g_ctx : A;

    const int lrow = tid >> 1;
    const int lq   = (tid & 1) * 16;

    const float* Ap = Abase + (size_t)(m0 + lrow) * K + lq;
    const float* Bp = Bw    + (size_t)(n0 + lrow) * K + lq;

    float4 ra[4], rb[4];
#pragma unroll
    for (int j = 0; j < 4; j++) {
        ra[j] = *(const float4*)(Ap + 4 * j);
        rb[j] = *(const float4*)(Bp + 4 * j);
    }

    float acc[4][4][4];
#pragma unroll
    for (int mi = 0; mi < 4; mi++)
#pragma unroll
        for (int ni = 0; ni < 4; ni++)
#pragma unroll
            for (int e = 0; e < 4; e++) acc[mi][ni][e] = 0.f;

    const int stBase = lrow * SSTR + lq;
    const int aBase = (wm * 64 + g) * SSTR + t;
    const int bBase = (wn * 32 + g) * SSTR + t;
    const int NT = K >> 5;

#pragma unroll
    for (int j = 0; j < 4; j++) {
        uint32_t* a = As + stBase + 4 * j;
        a[0] = f2tf32(ra[j].x); a[1] = f2tf32(ra[j].y);
        a[2] = f2tf32(ra[j].z); a[3] = f2tf32(ra[j].w);
        uint32_t* b = Bs + stBase + 4 * j;
        b[0] = f2tf32(rb[j].x); b[1] = f2tf32(rb[j].y);
        b[2] = f2tf32(rb[j].z); b[3] = f2tf32(rb[j].w);
    }
    __syncthreads();

    for (int kt = 0; kt < NT; kt++) {
        if (kt + 1 < NT) {
            Ap += 32; Bp += 32;
#pragma unroll
            for (int j = 0; j < 4; j++) {
                ra[j] = *(const float4*)(Ap + 4 * j);
                rb[j] = *(const float4*)(Bp + 4 * j);
            }
        }
        const uint32_t* a = As + (kt & 1) * TBUF;
        const uint32_t* b = Bs + (kt & 1) * TBUF;
#pragma unroll
        for (int kc = 0; kc < 32; kc += 8) {
            uint32_t af[4][4], bf[4][2];
#pragma unroll
            for (int mi = 0; mi < 4; mi++) {
                int base = aBase + mi * 16 * SSTR + kc;
                af[mi][0] = a[base];
                af[mi][1] = a[base + 8 * SSTR];
                af[mi][2] = a[base + 4];
                af[mi][3] = a[base + 8 * SSTR + 4];
            }
#pragma unroll
            for (int ni = 0; ni < 4; ni++) {
                int base = bBase + ni * 8 * SSTR + kc;
                bf[ni][0] = b[base];
                bf[ni][1] = b[base + 4];
            }
#pragma unroll
            for (int mi = 0; mi < 4; mi++)
#pragma unroll
                for (int ni = 0; ni < 4; ni++)
                    mma_tf32(acc[mi][ni], af[mi], bf[ni]);
        }
        if (kt + 1 < NT) {
            uint32_t* an = As + ((kt + 1) & 1) * TBUF + stBase;
            uint32_t* bn = Bs + ((kt + 1) & 1) * TBUF + stBase;
#pragma unroll
            for (int j = 0; j < 4; j++) {
                an[4*j+0] = f2tf32(ra[j].x); an[4*j+1] = f2tf32(ra[j].y);
                an[4*j+2] = f2tf32(ra[j].z); an[4*j+3] = f2tf32(ra[j].w);
                bn[4*j+0] = f2tf32(rb[j].x); bn[4*j+1] = f2tf32(rb[j].y);
                bn[4*j+2] = f2tf32(rb[j].z); bn[4*j+3] = f2tf32(rb[j].w);
            }
            __syncthreads();
        }
    }

#pragma unroll
    for (int mi = 0; mi < 4; mi++) {
        int r0 = m0 + wm * 64 + mi * 16 + g;
#pragma unroll
        for (int ni = 0; ni < 4; ni++) {
            int c0 = n0 + wn * 32 + ni * 8 + 2 * t;
#pragma unroll
            for (int e = 0; e < 4; e++) {
                int m = r0 + (e >> 1) * 8;
                int n = c0 + (e & 1);
                float v = acc[mi][ni][e] + __ldg(&bias[n]);
                if (MODE == 0) {
                    int b_ = m >> 11, s = m & (Sk - 1);
                    int h = n / 192, tt = n - h * 192;
                    int sel = tt >> 6, d = tt & 63;
                    float* dst = (sel == 0) ? g_Q : ((sel == 1) ? g_K : g_V);
                    dst[((size_t)((b_ << 4) + h) * Sk + s) * HDk + d] = v;
                } else {
                    Cout[(size_t)m * N + n] = v;
                }
            }
        }
    }
}

// ---------------------------------------------------------------------------
// Mask bit-packing: mask[2048][2048] int32 -> g_mbits[2048][64] u32
// ---------------------------------------------------------------------------
__global__ void pack_mask(const int* __restrict__ mask)
{
    int idx = blockIdx.x * 256 + threadIdx.x;   // q*64 + word
    const int4* p = (const int4*)(mask + (size_t)idx * 32);
    uint32_t bits = 0;
#pragma unroll
    for (int j = 0; j < 8; j++) {
        int4 v = p[j];
        bits |= (v.x != 0 ? 1u : 0u) << (j * 4 + 0);
        bits |= (v.y != 0 ? 1u : 0u) << (j * 4 + 1);
        bits |= (v.z != 0 ? 1u : 0u) << (j * 4 + 2);
        bits |= (v.w != 0 ? 1u : 0u) << (j * 4 + 3);
    }
    g_mbits[idx] = bits;
}

// ---------------------------------------------------------------------------
// Tensor-core flash attention.
// Block = 128 threads (4 warps), 64 q-rows (16/warp), loop over 64-key tiles.
// QK^T: 2xTF32 (Q hi/lo split), PV: fp16 mma with fp32 accum.
// ---------------------------------------------------------------------------
__global__ __launch_bounds__(128, 3) void flash_tc()
{
    __shared__ float    Qs[64 * 72];   // [row][d] scaled fp32
    __shared__ uint32_t Kt[64 * 72];   // [d][k] tf32
    __shared__ uint32_t Vt[64 * 36];   // [d][k] fp16 pairs

    const int tid = threadIdx.x;
    const int w = tid >> 5, lane = tid & 31;
    const int g = lane >> 2, t = lane & 3;
    const int bh = blockIdx.y;
    const int q0b = blockIdx.x * 64;

    const float* Qg = g_Q + (size_t)bh * Sk * HDk;
    const float* Kg = g_K + (size_t)bh * Sk * HDk;
    const float* Vg = g_V + (size_t)bh * Sk * HDk;

    // stage Q (pre-scaled by 1/sqrt(hd))
#pragma unroll
    for (int it = 0; it < 8; it++) {
        int idx = it * 128 + tid;
        int row = idx >> 4, c4 = (idx & 15) * 4;
        float4 v = *(const float4*)(Qg + (size_t)(q0b + row) * HDk + c4);
        v.x *= 0.125f; v.y *= 0.125f; v.z *= 0.125f; v.w *= 0.125f;
        *(float4*)&Qs[row * 72 + c4] = v;
    }
    __syncthreads();

    // Q fragments, hi/lo tf32 split (Dekker): rows w*16+g(+8), cols dc*8+t(+4)
    uint32_t qh[8][4], ql[8][4];
#pragma unroll
    for (int dc = 0; dc < 8; dc++)
#pragma unroll
        for (int e = 0; e < 4; e++) {
            int row = w * 16 + g + (e & 1) * 8;
            int col = dc * 8 + t + (e >> 1) * 4;
            float x = Qs[row * 72 + col];
            uint32_t hi = f2tf32(x);
            qh[dc][e] = hi;
            ql[dc][e] = f2tf32(x - __uint_as_float(hi));
        }

    float m0 = -INFINITY, m1 = -INFINITY, l0 = 0.f, l1 = 0.f;
    float o[8][4];
#pragma unroll
    for (int nf = 0; nf < 8; nf++)
#pragma unroll
        for (int e = 0; e < 4; e++) o[nf][e] = 0.f;

    const uint32_t* mr0 = g_mbits + (size_t)(q0b + w * 16 + g) * 64;
    const uint32_t* mr1 = mr0 + 8 * 64;

    for (int kt = 0; kt < Sk / 64; kt++) {
        // stage K (tf32, transposed) and V (fp16, transposed)
#pragma unroll
        for (int it = 0; it < 8; it++) {
            int idx = it * 128 + tid;
            int k = idx & 63, d4 = (idx >> 6) * 4;
            const float4 kv = *(const float4*)(Kg + (size_t)(kt * 64 + k) * HDk + d4);
            Kt[(d4 + 0) * 72 + k] = f2tf32(kv.x);
            Kt[(d4 + 1) * 72 + k] = f2tf32(kv.y);
            Kt[(d4 + 2) * 72 + k] = f2tf32(kv.z);
            Kt[(d4 + 3) * 72 + k] = f2tf32(kv.w);
            const float4 vv = *(const float4*)(Vg + (size_t)(kt * 64 + k) * HDk + d4);
            __half* Vh = (__half*)Vt;
            Vh[(d4 + 0) * 72 + k] = __float2half(vv.x);
            Vh[(d4 + 1) * 72 + k] = __float2half(vv.y);
            Vh[(d4 + 2) * 72 + k] = __float2half(vv.z);
            Vh[(d4 + 3) * 72 + k] = __float2half(vv.w);
        }
        uint32_t mw00 = mr0[kt * 2], mw01 = mr0[kt * 2 + 1];
        uint32_t mw10 = mr1[kt * 2], mw11 = mr1[kt * 2 + 1];
        __syncthreads();

        // S = Q K^T  (2xTF32)
        float c[8][4];
#pragma unroll
        for (int nf = 0; nf < 8; nf++)
#pragma unroll
            for (int e = 0; e < 4; e++) c[nf][e] = 0.f;
#pragma unroll
        for (int dc = 0; dc < 8; dc++) {
#pragma unroll
            for (int nf = 0; nf < 8; nf++) {
                uint32_t b[2];
                b[0] = Kt[(dc * 8 + t) * 72 + nf * 8 + g];
                b[1] = Kt[(dc * 8 + t + 4) * 72 + nf * 8 + g];
                mma_tf32(c[nf], qh[dc], b);
                mma_tf32(c[nf], ql[dc], b);
            }
        }

        // mask + row max
        float tm0 = -INFINITY, tm1 = -INFINITY;
#pragma unroll
        for (int nf = 0; nf < 8; nf++) {
            int cbit = (nf & 3) * 8 + 2 * t;
            uint32_t w0 = (nf < 4) ? mw00 : mw01;
            uint32_t w1 = (nf < 4) ? mw10 : mw11;
            c[nf][0] = ((w0 >> cbit) & 1)       ? c[nf][0] : NEG_INF;
            c[nf][1] = ((w0 >> (cbit + 1)) & 1) ? c[nf][1] : NEG_INF;
            c[nf][2] = ((w1 >> cbit) & 1)       ? c[nf][2] : NEG_INF;
            c[nf][3] = ((w1 >> (cbit + 1)) & 1) ? c[nf][3] : NEG_INF;
            tm0 = fmaxf(tm0, fmaxf(c[nf][0], c[nf][1]));
            tm1 = fmaxf(tm1, fmaxf(c[nf][2], c[nf][3]));
        }
        tm0 = fmaxf(tm0, __shfl_xor_sync(0xffffffffu, tm0, 1));
        tm0 = fmaxf(tm0, __shfl_xor_sync(0xffffffffu, tm0, 2));
        tm1 = fmaxf(tm1, __shfl_xor_sync(0xffffffffu, tm1, 1));
        tm1 = fmaxf(tm1, __shfl_xor_sync(0xffffffffu, tm1, 2));

        float mn0 = fmaxf(m0, tm0), mn1 = fmaxf(m1, tm1);
        float cr0 = __expf(m0 - mn0), cr1 = __expf(m1 - mn1);
        m0 = mn0; m1 = mn1;

        float rs0 = 0.f, rs1 = 0.f;
        uint32_t ph[8][2];
#pragma unroll
        for (int nf = 0; nf < 8; nf++) {
            float p0 = __expf(c[nf][0] - mn0);
            float p1 = __expf(c[nf][1] - mn0);
            float p2 = __expf(c[nf][2] - mn1);
            float p3 = __expf(c[nf][3] - mn1);
            rs0 += p0 + p1; rs1 += p2 + p3;
            __half2 h01 = __floats2half2_rn(p0, p1);
            __half2 h23 = __floats2half2_rn(p2, p3);
            ph[nf][0] = *reinterpret_cast<uint32_t*>(&h01);
            ph[nf][1] = *reinterpret_cast<uint32_t*>(&h23);
        }
        rs0 += __shfl_xor_sync(0xffffffffu, rs0, 1);
        rs0 += __shfl_xor_sync(0xffffffffu, rs0, 2);
        rs1 += __shfl_xor_sync(0xffffffffu, rs1, 1);
        rs1 += __shfl_xor_sync(0xffffffffu, rs1, 2);
        l0 = l0 * cr0 + rs0;
        l1 = l1 * cr1 + rs1;
#pragma unroll
        for (int nf = 0; nf < 8; nf++) {
            o[nf][0] *= cr0; o[nf][1] *= cr0;
            o[nf][2] *= cr1; o[nf][3] *= cr1;
        }

        // O += P V  (fp16 mma; P fragments come straight from QK accumulators)
#pragma unroll
        for (int ks = 0; ks < 4; ks++) {
            uint32_t a[4] = { ph[2*ks][0], ph[2*ks][1], ph[2*ks+1][0], ph[2*ks+1][1] };
#pragma unroll
            for (int nf = 0; nf < 8; nf++) {
                uint32_t b[2];
                int base = (nf * 8 + g) * 36 + 8 * ks + t;
                b[0] = Vt[base];
                b[1] = Vt[base + 4];
                mma_f16(o[nf], a, b);
            }
        }
        __syncthreads();
    }

    // epilogue: ctx[b, q, h*64 + d] = o / l
    const int b_ = bh >> 4, h = bh & 15;
    const float iv0 = 1.f / l0, iv1 = 1.f / l1;
    const int q_0 = q0b + w * 16 + g;
#pragma unroll
    for (int nf = 0; nf < 8; nf++) {
        int d = h * 64 + nf * 8 + 2 * t;
        float2 v0 = { o[nf][0] * iv0, o[nf][1] * iv0 };
        float2 v1 = { o[nf][2] * iv1, o[nf][3] * iv1 };
        *(float2*)&g_ctx[(size_t)(b_ * Sk + q_0    ) * Dk + d] = v0;
        *(float2*)&g_ctx[(size_t)(b_ * Sk + q_0 + 8) * Dk + d] = v1;
    }
}

// ---------------------------------------------------------------------------
extern "C" void kernel_launch(void* const* d_in, const int* in_sizes, int n_in,
                              void* d_out, int out_size)
{
    const float* x     = (const float*)d_in[0];
    const int*   mask  = (const int*)  d_in[1];
    const float* w_qkv = (const float*)d_in[2];
    const float* b_qkv = (const float*)d_in[3];
    const float* w_o   = (const float*)d_in[4];
    const float* b_o   = (const float*)d_in[5];
    float* out = (float*)d_out;

    const int gsmem = 4 * TBUF * (int)sizeof(uint32_t);
    cudaFuncSetAttribute(gemm_tc<0>, cudaFuncAttributeMaxDynamicSharedMemorySize, gsmem);
    cudaFuncSetAttribute(gemm_tc<1>, cudaFuncAttributeMaxDynamicSharedMemorySize, gsmem);

    // 0) pack mask bits
    pack_mask<<<(Sk * 64) / 256, 256>>>(mask);

    // 1) QKV projection + head scatter (TF32 tensor cores)
    gemm_tc<0><<<dim3((3 * Dk) / 128, (Bk * Sk) / 128), 256, gsmem>>>(
        x, w_qkv, b_qkv, nullptr, Bk * Sk, 3 * Dk, Dk);

    // 2) Tensor-core flash attention
    flash_tc<<<dim3(Sk / 64, Bk * Hk), 128>>>();

    // 3) Output projection (TF32 tensor cores)
    gemm_tc<1><<<dim3(Dk / 128, (Bk * Sk) / 128), 256, gsmem>>>(
        x /*ignored*/, w_o, b_o, out, Bk * Sk, Dk, Dk);
}

// round 4
// speedup vs baseline: 2.0543x; 1.1316x over previous
#include <cuda_runtime.h>
#include <cuda_fp16.h>
#include <math.h>
#include <stdint.h>

#define Bk 2
#define Sk 2048
#define Dk 1024
#define Hk 16
#define HDk 64
#define NEG_INF -9.0e15f

// Scratch (allocation-free rule: __device__ globals)
__device__ float g_Q[Bk*Hk*Sk*HDk];
__device__ float g_K[Bk*Hk*Sk*HDk];
__device__ float g_V[Bk*Hk*Sk*HDk];
__device__ float g_ctx[Bk*Sk*Dk];
__device__ uint32_t g_mbits[Sk * (Sk / 32)];

__device__ __forceinline__ uint32_t f2tf32(float f) {
    uint32_t u;
    asm("cvt.rna.tf32.f32 %0, %1;" : "=r"(u) : "f"(f));
    return u;
}

__device__ __forceinline__ void mma_tf32(float c[4], const uint32_t a[4], const uint32_t b[2]) {
    asm volatile(
        "mma.sync.aligned.m16n8k8.row.col.f32.tf32.tf32.f32 "
        "{%0,%1,%2,%3},{%4,%5,%6,%7},{%8,%9},{%0,%1,%2,%3};"
        : "+f"(c[0]), "+f"(c[1]), "+f"(c[2]), "+f"(c[3])
        : "r"(a[0]), "r"(a[1]), "r"(a[2]), "r"(a[3]), "r"(b[0]), "r"(b[1]));
}

__device__ __forceinline__ void mma_f16(float c[4], const uint32_t a[4], const uint32_t b[2]) {
    asm volatile(
        "mma.sync.aligned.m16n8k16.row.col.f32.f16.f16.f32 "
        "{%0,%1,%2,%3},{%4,%5,%6,%7},{%8,%9},{%0,%1,%2,%3};"
        : "+f"(c[0]), "+f"(c[1]), "+f"(c[2]), "+f"(c[3])
        : "r"(a[0]), "r"(a[1]), "r"(a[2]), "r"(a[3]), "r"(b[0]), "r"(b[1]));
}

__device__ __forceinline__ uint32_t h2bits(__half2 h) {
    return *reinterpret_cast<uint32_t*>(&h);
}

// ---------------------------------------------------------------------------
// TF32 tensor-core NT GEMM: C[m,n] = sum_k A[m,k]*B[n,k] + bias[n]
// Block 128x64, BK=32 double-buffered, 256 thr (8 warps of 32x32) -> 2 CTAs/SM.
// ---------------------------------------------------------------------------
#define SSTR 36
#define ABUF (128 * SSTR)
#define BBUF (64 * SSTR)

template<int MODE>
__global__ __launch_bounds__(256, 2) void gemm_tc(
    const float* __restrict__ A, const float* __restrict__ Bw,
    const float* __restrict__ bias, float* __restrict__ Cout,
    int M, int N, int K)
{
    extern __shared__ uint32_t sh[];
    uint32_t* As = sh;                  // [2][128][36]
    uint32_t* Bs = sh + 2 * ABUF;       // [2][64][36]

    const int tid = threadIdx.x;
    const int wid = tid >> 5, lane = tid & 31;
    const int g = lane >> 2, t = lane & 3;
    const int wm = wid >> 1, wn = wid & 1;
    const int m0 = blockIdx.y * 128, n0 = blockIdx.x * 64;

    const float* Abase = (MODE == 1) ? g_ctx : A;

    const int lrowA = tid >> 1, lqA = (tid & 1) * 16;
    const int lrowB = tid >> 2, lqB = (tid & 3) * 8;

    const float* Ap = Abase + (size_t)(m0 + lrowA) * K + lqA;
    const float* Bp = Bw    + (size_t)(n0 + lrowB) * K + lqB;

    float4 ra[4], rb[2];
#pragma unroll
    for (int j = 0; j < 4; j++) ra[j] = *(const float4*)(Ap + 4 * j);
#pragma unroll
    for (int j = 0; j < 2; j++) rb[j] = *(const float4*)(Bp + 4 * j);

    float acc[2][4][4];
#pragma unroll
    for (int mi = 0; mi < 2; mi++)
#pragma unroll
        for (int ni = 0; ni < 4; ni++)
#pragma unroll
            for (int e = 0; e < 4; e++) acc[mi][ni][e] = 0.f;

    const int stA = lrowA * SSTR + lqA;
    const int stB = lrowB * SSTR + lqB;
    const int aBase = (wm * 32 + g) * SSTR + t;
    const int bBase = (wn * 32 + g) * SSTR + t;
    const int NT = K >> 5;

#pragma unroll
    for (int j = 0; j < 4; j++) {
        uint32_t* a = As + stA + 4 * j;
        a[0] = f2tf32(ra[j].x); a[1] = f2tf32(ra[j].y);
        a[2] = f2tf32(ra[j].z); a[3] = f2tf32(ra[j].w);
    }
#pragma unroll
    for (int j = 0; j < 2; j++) {
        uint32_t* b = Bs + stB + 4 * j;
        b[0] = f2tf32(rb[j].x); b[1] = f2tf32(rb[j].y);
        b[2] = f2tf32(rb[j].z); b[3] = f2tf32(rb[j].w);
    }
    __syncthreads();

    for (int kt = 0; kt < NT; kt++) {
        if (kt + 1 < NT) {
            Ap += 32; Bp += 32;
#pragma unroll
            for (int j = 0; j < 4; j++) ra[j] = *(const float4*)(Ap + 4 * j);
#pragma unroll
            for (int j = 0; j < 2; j++) rb[j] = *(const float4*)(Bp + 4 * j);
        }
        const uint32_t* a = As + (kt & 1) * ABUF;
        const uint32_t* b = Bs + (kt & 1) * BBUF;
#pragma unroll
        for (int kc = 0; kc < 32; kc += 8) {
            uint32_t af[2][4], bf[4][2];
#pragma unroll
            for (int mi = 0; mi < 2; mi++) {
                int base = aBase + mi * 16 * SSTR + kc;
                af[mi][0] = a[base];
                af[mi][1] = a[base + 8 * SSTR];
                af[mi][2] = a[base + 4];
                af[mi][3] = a[base + 8 * SSTR + 4];
            }
#pragma unroll
            for (int ni = 0; ni < 4; ni++) {
                int base = bBase + ni * 8 * SSTR + kc;
                bf[ni][0] = b[base];
                bf[ni][1] = b[base + 4];
            }
#pragma unroll
            for (int mi = 0; mi < 2; mi++)
#pragma unroll
                for (int ni = 0; ni < 4; ni++)
                    mma_tf32(acc[mi][ni], af[mi], bf[ni]);
        }
        if (kt + 1 < NT) {
            uint32_t* an = As + ((kt + 1) & 1) * ABUF + stA;
            uint32_t* bn = Bs + ((kt + 1) & 1) * BBUF + stB;
#pragma unroll
            for (int j = 0; j < 4; j++) {
                an[4*j+0] = f2tf32(ra[j].x); an[4*j+1] = f2tf32(ra[j].y);
                an[4*j+2] = f2tf32(ra[j].z); an[4*j+3] = f2tf32(ra[j].w);
            }
#pragma unroll
            for (int j = 0; j < 2; j++) {
                bn[4*j+0] = f2tf32(rb[j].x); bn[4*j+1] = f2tf32(rb[j].y);
                bn[4*j+2] = f2tf32(rb[j].z); bn[4*j+3] = f2tf32(rb[j].w);
            }
            __syncthreads();
        }
    }

#pragma unroll
    for (int mi = 0; mi < 2; mi++) {
        int r0 = m0 + wm * 32 + mi * 16 + g;
#pragma unroll
        for (int ni = 0; ni < 4; ni++) {
            int c0 = n0 + wn * 32 + ni * 8 + 2 * t;
#pragma unroll
            for (int e = 0; e < 4; e++) {
                int m = r0 + (e >> 1) * 8;
                int n = c0 + (e & 1);
                float v = acc[mi][ni][e] + __ldg(&bias[n]);
                if (MODE == 0) {
                    int b_ = m >> 11, s = m & (Sk - 1);
                    int h = n / 192, tt = n - h * 192;
                    int sel = tt >> 6, d = tt & 63;
                    float* dst = (sel == 0) ? g_Q : ((sel == 1) ? g_K : g_V);
                    dst[((size_t)((b_ << 4) + h) * Sk + s) * HDk + d] = v;
                } else {
                    Cout[(size_t)m * N + n] = v;
                }
            }
        }
    }
}

// ---------------------------------------------------------------------------
// Mask bit-packing: mask[2048][2048] int32 -> g_mbits[2048][64] u32
// ---------------------------------------------------------------------------
__global__ void pack_mask(const int* __restrict__ mask)
{
    int idx = blockIdx.x * 256 + threadIdx.x;
    const int4* p = (const int4*)(mask + (size_t)idx * 32);
    uint32_t bits = 0;
#pragma unroll
    for (int j = 0; j < 8; j++) {
        int4 v = p[j];
        bits |= (v.x != 0 ? 1u : 0u) << (j * 4 + 0);
        bits |= (v.y != 0 ? 1u : 0u) << (j * 4 + 1);
        bits |= (v.z != 0 ? 1u : 0u) << (j * 4 + 2);
        bits |= (v.w != 0 ? 1u : 0u) << (j * 4 + 3);
    }
    g_mbits[idx] = bits;
}

// ---------------------------------------------------------------------------
// Flash attention, all-fp16 tensor path, softmax in log2 space.
// Block = 128 thr (4 warps), 64 q-rows, 64-key tiles.
// QK: 2xFP16 (Q hi+lo Dekker); PV: fp16 with fp32 accum; row-sum via ones-cols.
// ---------------------------------------------------------------------------
__global__ __launch_bounds__(128, 3) void flash_tc()
{
    __shared__ float    Qs[64 * 72];    // [q-row][d] fp32, scaled by 0.125*log2e
    __shared__ uint32_t Ktp[32 * 72];   // [d-pair][key] half2(d, d+1)
    __shared__ uint32_t Vt[72 * 36];    // [d][key-pair] half2(k, k+1); rows 64-71 = ones

    const int tid = threadIdx.x;
    const int w = tid >> 5, lane = tid & 31;
    const int g = lane >> 2, t = lane & 3;
    const int bh = blockIdx.y;
    const int q0b = blockIdx.x * 64;

    const float* Qg = g_Q + (size_t)bh * Sk * HDk;
    const float* Kg = g_K + (size_t)bh * Sk * HDk;
    const float* Vg = g_V + (size_t)bh * Sk * HDk;

    // stage Q (pre-scaled by 1/sqrt(hd) * log2(e))
    const float QSCALE = 0.125f * 1.4426950408889634f;
#pragma unroll
    for (int it = 0; it < 8; it++) {
        int idx = it * 128 + tid;
        int row = idx >> 4, c4 = (idx & 15) * 4;
        float4 v = *(const float4*)(Qg + (size_t)(q0b + row) * HDk + c4);
        v.x *= QSCALE; v.y *= QSCALE; v.z *= QSCALE; v.w *= QSCALE;
        *(float4*)&Qs[row * 72 + c4] = v;
    }
    // ones block for row-sum accumulator (V rows 64-71, value half2(1,1))
    for (int i = tid; i < 8 * 36; i += 128) Vt[64 * 36 + i] = 0x3C003C00u;
    __syncthreads();

    // Q fragments: hi (fp16) + lo (fp16 residual), m16n8k16 A layout
    uint32_t qh[4][4], ql[4][4];
#pragma unroll
    for (int dc = 0; dc < 4; dc++)
#pragma unroll
        for (int e = 0; e < 4; e++) {
            int row = w * 16 + g + (e & 1) * 8;
            int col = dc * 16 + (e >> 1) * 8 + 2 * t;
            float x0 = Qs[row * 72 + col], x1 = Qs[row * 72 + col + 1];
            __half2 h = __floats2half2_rn(x0, x1);
            qh[dc][e] = h2bits(h);
            float2 hf = __half22float2(h);
            ql[dc][e] = h2bits(__floats2half2_rn(x0 - hf.x, x1 - hf.y));
        }

    float m0 = -INFINITY, m1 = -INFINITY;
    float o[9][4];
#pragma unroll
    for (int nf = 0; nf < 9; nf++)
#pragma unroll
        for (int e = 0; e < 4; e++) o[nf][e] = 0.f;

    const uint32_t* mr0 = g_mbits + (size_t)(q0b + w * 16 + g) * 64;
    const uint32_t* mr1 = mr0 + 8 * 64;

    for (int kt = 0; kt < Sk / 64; kt++) {
        // stage K (half2 pairs along d) and V (half2 pairs along k)
#pragma unroll
        for (int it = 0; it < 8; it++) {
            int idx = it * 128 + tid;
            int k = idx & 63, d4 = (idx >> 6) * 4;
            const float4 kv = *(const float4*)(Kg + (size_t)(kt * 64 + k) * HDk + d4);
            Ktp[((d4 >> 1) + 0) * 72 + k] = h2bits(__floats2half2_rn(kv.x, kv.y));
            Ktp[((d4 >> 1) + 1) * 72 + k] = h2bits(__floats2half2_rn(kv.z, kv.w));
            const float4 vv = *(const float4*)(Vg + (size_t)(kt * 64 + k) * HDk + d4);
            __half* Vh = (__half*)Vt;
            Vh[(d4 + 0) * 72 + k] = __float2half(vv.x);
            Vh[(d4 + 1) * 72 + k] = __float2half(vv.y);
            Vh[(d4 + 2) * 72 + k] = __float2half(vv.z);
            Vh[(d4 + 3) * 72 + k] = __float2half(vv.w);
        }
        uint32_t mw00 = mr0[kt * 2], mw01 = mr0[kt * 2 + 1];
        uint32_t mw10 = mr1[kt * 2], mw11 = mr1[kt * 2 + 1];
        __syncthreads();

        // S = Q K^T  (2xFP16, fp32 accum, log2-scaled)
        float c[8][4];
#pragma unroll
        for (int nf = 0; nf < 8; nf++)
#pragma unroll
            for (int e = 0; e < 4; e++) c[nf][e] = 0.f;
#pragma unroll
        for (int dc = 0; dc < 4; dc++) {
#pragma unroll
            for (int nf = 0; nf < 8; nf++) {
                uint32_t b[2];
                b[0] = Ktp[(dc * 8 + t) * 72 + nf * 8 + g];
                b[1] = Ktp[(dc * 8 + t + 4) * 72 + nf * 8 + g];
                mma_f16(c[nf], qh[dc], b);
                mma_f16(c[nf], ql[dc], b);
            }
        }

        // mask + row max
        float tm0 = -INFINITY, tm1 = -INFINITY;
#pragma unroll
        for (int nf = 0; nf < 8; nf++) {
            int cbit = (nf & 3) * 8 + 2 * t;
            uint32_t w0 = (nf < 4) ? mw00 : mw01;
            uint32_t w1 = (nf < 4) ? mw10 : mw11;
            c[nf][0] = ((w0 >> cbit) & 1)       ? c[nf][0] : NEG_INF;
            c[nf][1] = ((w0 >> (cbit + 1)) & 1) ? c[nf][1] : NEG_INF;
            c[nf][2] = ((w1 >> cbit) & 1)       ? c[nf][2] : NEG_INF;
            c[nf][3] = ((w1 >> (cbit + 1)) & 1) ? c[nf][3] : NEG_INF;
            tm0 = fmaxf(tm0, fmaxf(c[nf][0], c[nf][1]));
            tm1 = fmaxf(tm1, fmaxf(c[nf][2], c[nf][3]));
        }
        tm0 = fmaxf(tm0, __shfl_xor_sync(0xffffffffu, tm0, 1));
        tm0 = fmaxf(tm0, __shfl_xor_sync(0xffffffffu, tm0, 2));
        tm1 = fmaxf(tm1, __shfl_xor_sync(0xffffffffu, tm1, 1));
        tm1 = fmaxf(tm1, __shfl_xor_sync(0xffffffffu, tm1, 2));

        float mn0 = fmaxf(m0, tm0), mn1 = fmaxf(m1, tm1);
        float cr0 = exp2f(m0 - mn0), cr1 = exp2f(m1 - mn1);
        m0 = mn0; m1 = mn1;

        // p = 2^(c - mn) directly in half2 (these ARE the PV fragments)
        uint32_t ph[8][2];
#pragma unroll
        for (int nf = 0; nf < 8; nf++) {
            __half2 a01 = __floats2half2_rn(c[nf][0] - mn0, c[nf][1] - mn0);
            __half2 a23 = __floats2half2_rn(c[nf][2] - mn1, c[nf][3] - mn1);
            ph[nf][0] = h2bits(h2exp2(a01));
            ph[nf][1] = h2bits(h2exp2(a23));
        }
#pragma unroll
        for (int nf = 0; nf < 9; nf++) {
            o[nf][0] *= cr0; o[nf][1] *= cr0;
            o[nf][2] *= cr1; o[nf][3] *= cr1;
        }

        // O += P V  (cols 64-71 accumulate row-sum l)
#pragma unroll
        for (int ks = 0; ks < 4; ks++) {
            uint32_t a[4] = { ph[2*ks][0], ph[2*ks][1], ph[2*ks+1][0], ph[2*ks+1][1] };
#pragma unroll
            for (int nf = 0; nf < 9; nf++) {
                uint32_t b[2];
                int base = (nf * 8 + g) * 36 + 8 * ks + t;
                b[0] = Vt[base];
                b[1] = Vt[base + 4];
                mma_f16(o[nf], a, b);
            }
        }
        __syncthreads();
    }

    // epilogue: l = ones-column accumulator; ctx[b, q, h*64 + d] = o / l
    const int b_ = bh >> 4, h = bh & 15;
    const float iv0 = 1.f / o[8][0], iv1 = 1.f / o[8][2];
    const int q_0 = q0b + w * 16 + g;
#pragma unroll
    for (int nf = 0; nf < 8; nf++) {
        int d = h * 64 + nf * 8 + 2 * t;
        float2 v0 = { o[nf][0] * iv0, o[nf][1] * iv0 };
        float2 v1 = { o[nf][2] * iv1, o[nf][3] * iv1 };
        *(float2*)&g_ctx[(size_t)(b_ * Sk + q_0    ) * Dk + d] = v0;
        *(float2*)&g_ctx[(size_t)(b_ * Sk + q_0 + 8) * Dk + d] = v1;
    }
}

// ---------------------------------------------------------------------------
extern "C" void kernel_launch(void* const* d_in, const int* in_sizes, int n_in,
                              void* d_out, int out_size)
{
    const float* x     = (const float*)d_in[0];
    const int*   mask  = (const int*)  d_in[1];
    const float* w_qkv = (const float*)d_in[2];
    const float* b_qkv = (const float*)d_in[3];
    const float* w_o   = (const float*)d_in[4];
    const float* b_o   = (const float*)d_in[5];
    float* out = (float*)d_out;

    const int gsmem = (2 * ABUF + 2 * BBUF) * (int)sizeof(uint32_t);  // 55296
    cudaFuncSetAttribute(gemm_tc<0>, cudaFuncAttributeMaxDynamicSharedMemorySize, gsmem);
    cudaFuncSetAttribute(gemm_tc<1>, cudaFuncAttributeMaxDynamicSharedMemorySize, gsmem);

    // 0) pack mask bits
    pack_mask<<<(Sk * 64) / 256, 256>>>(mask);

    // 1) QKV projection + head scatter (TF32 tensor cores, 2 CTAs/SM)
    gemm_tc<0><<<dim3((3 * Dk) / 64, (Bk * Sk) / 128), 256, gsmem>>>(
        x, w_qkv, b_qkv, nullptr, Bk * Sk, 3 * Dk, Dk);

    // 2) Flash attention (fp16 tensor cores)
    flash_tc<<<dim3(Sk / 64, Bk * Hk), 128>>>();

    // 3) Output projection (TF32 tensor cores)
    gemm_tc<1><<<dim3(Dk / 64, (Bk * Sk) / 128), 256, gsmem>>>(
        x /*ignored*/, w_o, b_o, out, Bk * Sk, Dk, Dk);
}

// round 5
// speedup vs baseline: 2.5490x; 1.2408x over previous
#include <cuda_runtime.h>
#include <cuda_fp16.h>
#include <math.h>
#include <stdint.h>

#define Bk 2
#define Sk 2048
#define Dk 1024
#define Hk 16
#define HDk 64
#define NEG_INF -9.0e15f

// Scratch (allocation-free rule: __device__ globals)
__device__ float    g_Q[Bk*Hk*Sk*HDk];
__device__ uint32_t g_Kh[Bk*Hk*Sk*32];   // half2 pairs along d, row-major [bh][s][32]
__device__ uint32_t g_Vh[Bk*Hk*Sk*32];
__device__ float    g_ctx[Bk*Sk*Dk];
__device__ uint32_t g_mbits[Sk * (Sk / 32)];

__device__ __forceinline__ uint32_t f2tf32(float f) {
    uint32_t u;
    asm("cvt.rna.tf32.f32 %0, %1;" : "=r"(u) : "f"(f));
    return u;
}

__device__ __forceinline__ void mma_tf32(float c[4], const uint32_t a[4], const uint32_t b[2]) {
    asm volatile(
        "mma.sync.aligned.m16n8k8.row.col.f32.tf32.tf32.f32 "
        "{%0,%1,%2,%3},{%4,%5,%6,%7},{%8,%9},{%0,%1,%2,%3};"
        : "+f"(c[0]), "+f"(c[1]), "+f"(c[2]), "+f"(c[3])
        : "r"(a[0]), "r"(a[1]), "r"(a[2]), "r"(a[3]), "r"(b[0]), "r"(b[1]));
}

__device__ __forceinline__ void mma_f16(float c[4], const uint32_t a[4], const uint32_t b[2]) {
    asm volatile(
        "mma.sync.aligned.m16n8k16.row.col.f32.f16.f16.f32 "
        "{%0,%1,%2,%3},{%4,%5,%6,%7},{%8,%9},{%0,%1,%2,%3};"
        : "+f"(c[0]), "+f"(c[1]), "+f"(c[2]), "+f"(c[3])
        : "r"(a[0]), "r"(a[1]), "r"(a[2]), "r"(a[3]), "r"(b[0]), "r"(b[1]));
}

__device__ __forceinline__ uint32_t h2bits(__half2 h) {
    return *reinterpret_cast<uint32_t*>(&h);
}

// ---------------------------------------------------------------------------
// TF32 tensor-core NT GEMM: C[m,n] = sum_k A[m,k]*B[n,k] + bias[n]
// Block 128x64, BK=16 double-buffered, 256 thr (8 warps of 32x32), 3 CTAs/SM.
// MODE 0 scatters Q (fp32) and K/V (fp16 half2) per head.
// ---------------------------------------------------------------------------
#define SSTR 20
#define ABUF (128 * SSTR)
#define BBUF (64 * SSTR)

template<int MODE>
__global__ __launch_bounds__(256, 3) void gemm_tc(
    const float* __restrict__ A, const float* __restrict__ Bw,
    const float* __restrict__ bias, float* __restrict__ Cout,
    int M, int N, int K)
{
    extern __shared__ uint32_t sh[];
    uint32_t* As = sh;                  // [2][128][20]
    uint32_t* Bs = sh + 2 * ABUF;       // [2][64][20]

    const int tid = threadIdx.x;
    const int wid = tid >> 5, lane = tid & 31;
    const int g = lane >> 2, t = lane & 3;
    const int wm = wid >> 1, wn = wid & 1;
    const int m0 = blockIdx.y * 128, n0 = blockIdx.x * 64;

    const float* Abase = (MODE == 1) ? g_ctx : A;

    const int lrowA = tid >> 1, lqA = (tid & 1) * 8;
    const int lrowB = tid >> 2, lqB = (tid & 3) * 4;

    const float* Ap = Abase + (size_t)(m0 + lrowA) * K + lqA;
    const float* Bp = Bw    + (size_t)(n0 + lrowB) * K + lqB;

    float4 ra[2], rb;
    ra[0] = *(const float4*)Ap;
    ra[1] = *(const float4*)(Ap + 4);
    rb    = *(const float4*)Bp;

    float acc[2][4][4];
#pragma unroll
    for (int mi = 0; mi < 2; mi++)
#pragma unroll
        for (int ni = 0; ni < 4; ni++)
#pragma unroll
            for (int e = 0; e < 4; e++) acc[mi][ni][e] = 0.f;

    const int stA = lrowA * SSTR + lqA;
    const int stB = lrowB * SSTR + lqB;
    const int aBase = (wm * 32 + g) * SSTR + t;
    const int bBase = (wn * 32 + g) * SSTR + t;
    const int NT = K >> 4;

    {
        uint32_t* a = As + stA;
        a[0] = f2tf32(ra[0].x); a[1] = f2tf32(ra[0].y);
        a[2] = f2tf32(ra[0].z); a[3] = f2tf32(ra[0].w);
        a[4] = f2tf32(ra[1].x); a[5] = f2tf32(ra[1].y);
        a[6] = f2tf32(ra[1].z); a[7] = f2tf32(ra[1].w);
        uint32_t* b = Bs + stB;
        b[0] = f2tf32(rb.x); b[1] = f2tf32(rb.y);
        b[2] = f2tf32(rb.z); b[3] = f2tf32(rb.w);
    }
    __syncthreads();

    for (int kt = 0; kt < NT; kt++) {
        if (kt + 1 < NT) {
            Ap += 16; Bp += 16;
            ra[0] = *(const float4*)Ap;
            ra[1] = *(const float4*)(Ap + 4);
            rb    = *(const float4*)Bp;
        }
        const uint32_t* a = As + (kt & 1) * ABUF;
        const uint32_t* b = Bs + (kt & 1) * BBUF;
#pragma unroll
        for (int kc = 0; kc < 16; kc += 8) {
            uint32_t af[2][4], bf[4][2];
#pragma unroll
            for (int mi = 0; mi < 2; mi++) {
                int base = aBase + mi * 16 * SSTR + kc;
                af[mi][0] = a[base];
                af[mi][1] = a[base + 8 * SSTR];
                af[mi][2] = a[base + 4];
                af[mi][3] = a[base + 8 * SSTR + 4];
            }
#pragma unroll
            for (int ni = 0; ni < 4; ni++) {
                int base = bBase + ni * 8 * SSTR + kc;
                bf[ni][0] = b[base];
                bf[ni][1] = b[base + 4];
            }
#pragma unroll
            for (int mi = 0; mi < 2; mi++)
#pragma unroll
                for (int ni = 0; ni < 4; ni++)
                    mma_tf32(acc[mi][ni], af[mi], bf[ni]);
        }
        if (kt + 1 < NT) {
            uint32_t* an = As + ((kt + 1) & 1) * ABUF + stA;
            uint32_t* bn = Bs + ((kt + 1) & 1) * BBUF + stB;
            an[0] = f2tf32(ra[0].x); an[1] = f2tf32(ra[0].y);
            an[2] = f2tf32(ra[0].z); an[3] = f2tf32(ra[0].w);
            an[4] = f2tf32(ra[1].x); an[5] = f2tf32(ra[1].y);
            an[6] = f2tf32(ra[1].z); an[7] = f2tf32(ra[1].w);
            bn[0] = f2tf32(rb.x); bn[1] = f2tf32(rb.y);
            bn[2] = f2tf32(rb.z); bn[3] = f2tf32(rb.w);
            __syncthreads();
        }
    }

    // Epilogue: process column pairs (n, n+1) — never straddles head/sel bounds
#pragma unroll
    for (int mi = 0; mi < 2; mi++) {
        int r0 = m0 + wm * 32 + mi * 16 + g;
#pragma unroll
        for (int ni = 0; ni < 4; ni++) {
            int n = n0 + wn * 32 + ni * 8 + 2 * t;
            float bi0 = __ldg(&bias[n]), bi1 = __ldg(&bias[n + 1]);
#pragma unroll
            for (int rp = 0; rp < 2; rp++) {
                int m = r0 + rp * 8;
                float v0 = acc[mi][ni][rp * 2 + 0] + bi0;
                float v1 = acc[mi][ni][rp * 2 + 1] + bi1;
                if (MODE == 0) {
                    int b_ = m >> 11, s = m & (Sk - 1);
                    int h = n / 192, tt = n - h * 192;
                    int sel = tt >> 6, d = tt & 63;
                    int bh = (b_ << 4) + h;
                    if (sel == 0) {
                        float2 q2 = {v0, v1};
                        *(float2*)&g_Q[((size_t)bh * Sk + s) * HDk + d] = q2;
                    } else {
                        uint32_t hv = h2bits(__floats2half2_rn(v0, v1));
                        uint32_t* dst = (sel == 1) ? g_Kh : g_Vh;
                        dst[((size_t)bh * Sk + s) * 32 + (d >> 1)] = hv;
                    }
                } else {
                    float2 c2 = {v0, v1};
                    *(float2*)&Cout[(size_t)m * N + n] = c2;
                }
            }
        }
    }
}

// ---------------------------------------------------------------------------
// Mask bit-packing: mask[2048][2048] int32 -> g_mbits[2048][64] u32
// ---------------------------------------------------------------------------
__global__ void pack_mask(const int* __restrict__ mask)
{
    int idx = blockIdx.x * 256 + threadIdx.x;
    const int4* p = (const int4*)(mask + (size_t)idx * 32);
    uint32_t bits = 0;
#pragma unroll
    for (int j = 0; j < 8; j++) {
        int4 v = p[j];
        bits |= (v.x != 0 ? 1u : 0u) << (j * 4 + 0);
        bits |= (v.y != 0 ? 1u : 0u) << (j * 4 + 1);
        bits |= (v.z != 0 ? 1u : 0u) << (j * 4 + 2);
        bits |= (v.w != 0 ? 1u : 0u) << (j * 4 + 3);
    }
    g_mbits[idx] = bits;
}

// ---------------------------------------------------------------------------
// Flash attention, all-fp16 tensor path, softmax in log2 space.
// Block = 128 thr (4 warps), 64 q-rows, 64-key tiles.
// K/V pre-converted to fp16 by gemm0 -> staging is pure copy/transpose.
// ---------------------------------------------------------------------------
__global__ __launch_bounds__(128, 3) void flash_tc()
{
    __shared__ uint32_t Ktp2[64 * 36];  // [key][dpair] half2(d,d+1)
    __shared__ uint32_t Vt[72 * 36];    // [d][kpair] half2(k,k+1); rows 64-71 = ones

    const int tid = threadIdx.x;
    const int w = tid >> 5, lane = tid & 31;
    const int g = lane >> 2, t = lane & 3;
    const int bh = blockIdx.y;
    const int q0b = blockIdx.x * 64;

    const float*    Qg  = g_Q  + (size_t)bh * Sk * HDk;
    const uint32_t* Khg = g_Kh + (size_t)bh * Sk * 32;
    const uint32_t* Vhg = g_Vh + (size_t)bh * Sk * 32;

    // ones block for row-sum accumulator (V rows 64-71)
    for (int i = tid; i < 8 * 36; i += 128) Vt[64 * 36 + i] = 0x3C003C00u;

    // Q fragments direct from gmem: hi + lo fp16 Dekker split, log2e-scaled
    const float QSCALE = 0.125f * 1.4426950408889634f;
    uint32_t qh[4][4], ql[4][4];
#pragma unroll
    for (int dc = 0; dc < 4; dc++)
#pragma unroll
        for (int e = 0; e < 4; e++) {
            int row = q0b + w * 16 + g + (e & 1) * 8;
            int col = dc * 16 + (e >> 1) * 8 + 2 * t;
            float2 q2 = *(const float2*)(Qg + (size_t)row * HDk + col);
            float x0 = q2.x * QSCALE, x1 = q2.y * QSCALE;
            __half2 h = __floats2half2_rn(x0, x1);
            qh[dc][e] = h2bits(h);
            float2 hf = __half22float2(h);
            ql[dc][e] = h2bits(__floats2half2_rn(x0 - hf.x, x1 - hf.y));
        }

    float m0 = -INFINITY, m1 = -INFINITY;
    float o[9][4];
#pragma unroll
    for (int nf = 0; nf < 9; nf++)
#pragma unroll
        for (int e = 0; e < 4; e++) o[nf][e] = 0.f;

    const uint32_t* mr0 = g_mbits + (size_t)(q0b + w * 16 + g) * 64;
    const uint32_t* mr1 = mr0 + 8 * 64;

    for (int kt = 0; kt < Sk / 64; kt++) {
        // K staging: pure copy into [key][dpair] (STS.128, conflict-free)
#pragma unroll
        for (int it = 0; it < 4; it++) {
            int idx = it * 128 + tid;
            int k = idx >> 3, dg = idx & 7;
            uint4 kv = *(const uint4*)(Khg + (size_t)(kt * 64 + k) * 32 + dg * 4);
            *(uint4*)&Ktp2[k * 36 + dg * 4] = kv;
        }
        // V staging: pair-transpose via byte_perm into [d][kpair]
#pragma unroll
        for (int it = 0; it < 2; it++) {
            int idx = it * 128 + tid;
            int kp = idx >> 3, dg = idx & 7;
            const uint32_t* vp = Vhg + (size_t)(kt * 64 + kp * 2) * 32 + dg * 4;
            uint4 va = *(const uint4*)vp;
            uint4 vb = *(const uint4*)(vp + 32);
            int d0 = dg * 8;
            Vt[(d0 + 0) * 36 + kp] = __byte_perm(va.x, vb.x, 0x5410);
            Vt[(d0 + 1) * 36 + kp] = __byte_perm(va.x, vb.x, 0x7632);
            Vt[(d0 + 2) * 36 + kp] = __byte_perm(va.y, vb.y, 0x5410);
            Vt[(d0 + 3) * 36 + kp] = __byte_perm(va.y, vb.y, 0x7632);
            Vt[(d0 + 4) * 36 + kp] = __byte_perm(va.z, vb.z, 0x5410);
            Vt[(d0 + 5) * 36 + kp] = __byte_perm(va.z, vb.z, 0x7632);
            Vt[(d0 + 6) * 36 + kp] = __byte_perm(va.w, vb.w, 0x5410);
            Vt[(d0 + 7) * 36 + kp] = __byte_perm(va.w, vb.w, 0x7632);
        }
        uint32_t mw00 = mr0[kt * 2], mw01 = mr0[kt * 2 + 1];
        uint32_t mw10 = mr1[kt * 2], mw11 = mr1[kt * 2 + 1];
        __syncthreads();

        // S = Q K^T  (2xFP16, fp32 accum, log2-scaled)
        float c[8][4];
#pragma unroll
        for (int nf = 0; nf < 8; nf++)
#pragma unroll
            for (int e = 0; e < 4; e++) c[nf][e] = 0.f;
#pragma unroll
        for (int dc = 0; dc < 4; dc++) {
#pragma unroll
            for (int nf = 0; nf < 8; nf++) {
                uint32_t b[2];
                int base = (nf * 8 + g) * 36 + dc * 8 + t;
                b[0] = Ktp2[base];
                b[1] = Ktp2[base + 4];
                mma_f16(c[nf], qh[dc], b);
                mma_f16(c[nf], ql[dc], b);
            }
        }

        // mask + row max
        float tm0 = -INFINITY, tm1 = -INFINITY;
#pragma unroll
        for (int nf = 0; nf < 8; nf++) {
            int cbit = (nf & 3) * 8 + 2 * t;
            uint32_t w0 = (nf < 4) ? mw00 : mw01;
            uint32_t w1 = (nf < 4) ? mw10 : mw11;
            c[nf][0] = ((w0 >> cbit) & 1)       ? c[nf][0] : NEG_INF;
            c[nf][1] = ((w0 >> (cbit + 1)) & 1) ? c[nf][1] : NEG_INF;
            c[nf][2] = ((w1 >> cbit) & 1)       ? c[nf][2] : NEG_INF;
            c[nf][3] = ((w1 >> (cbit + 1)) & 1) ? c[nf][3] : NEG_INF;
            tm0 = fmaxf(tm0, fmaxf(c[nf][0], c[nf][1]));
            tm1 = fmaxf(tm1, fmaxf(c[nf][2], c[nf][3]));
        }
        tm0 = fmaxf(tm0, __shfl_xor_sync(0xffffffffu, tm0, 1));
        tm0 = fmaxf(tm0, __shfl_xor_sync(0xffffffffu, tm0, 2));
        tm1 = fmaxf(tm1, __shfl_xor_sync(0xffffffffu, tm1, 1));
        tm1 = fmaxf(tm1, __shfl_xor_sync(0xffffffffu, tm1, 2));

        float mn0 = fmaxf(m0, tm0), mn1 = fmaxf(m1, tm1);
        float cr0 = exp2f(m0 - mn0), cr1 = exp2f(m1 - mn1);
        m0 = mn0; m1 = mn1;

        // p = 2^(c - mn) directly in half2 (these ARE the PV fragments)
        uint32_t ph[8][2];
#pragma unroll
        for (int nf = 0; nf < 8; nf++) {
            __half2 a01 = __floats2half2_rn(c[nf][0] - mn0, c[nf][1] - mn0);
            __half2 a23 = __floats2half2_rn(c[nf][2] - mn1, c[nf][3] - mn1);
            ph[nf][0] = h2bits(h2exp2(a01));
            ph[nf][1] = h2bits(h2exp2(a23));
        }
#pragma unroll
        for (int nf = 0; nf < 9; nf++) {
            o[nf][0] *= cr0; o[nf][1] *= cr0;
            o[nf][2] *= cr1; o[nf][3] *= cr1;
        }

        // O += P V  (cols 64-71 accumulate row-sum l)
#pragma unroll
        for (int ks = 0; ks < 4; ks++) {
            uint32_t a[4] = { ph[2*ks][0], ph[2*ks][1], ph[2*ks+1][0], ph[2*ks+1][1] };
#pragma unroll
            for (int nf = 0; nf < 9; nf++) {
                uint32_t b[2];
                int base = (nf * 8 + g) * 36 + 8 * ks + t;
                b[0] = Vt[base];
                b[1] = Vt[base + 4];
                mma_f16(o[nf], a, b);
            }
        }
        __syncthreads();
    }

    // epilogue: l = ones-column accumulator; ctx[b, q, h*64 + d] = o / l
    const int b_ = bh >> 4, h = bh & 15;
    const float iv0 = 1.f / o[8][0], iv1 = 1.f / o[8][2];
    const int q_0 = q0b + w * 16 + g;
#pragma unroll
    for (int nf = 0; nf < 8; nf++) {
        int d = h * 64 + nf * 8 + 2 * t;
        float2 v0 = { o[nf][0] * iv0, o[nf][1] * iv0 };
        float2 v1 = { o[nf][2] * iv1, o[nf][3] * iv1 };
        *(float2*)&g_ctx[(size_t)(b_ * Sk + q_0    ) * Dk + d] = v0;
        *(float2*)&g_ctx[(size_t)(b_ * Sk + q_0 + 8) * Dk + d] = v1;
    }
}

// ---------------------------------------------------------------------------
extern "C" void kernel_launch(void* const* d_in, const int* in_sizes, int n_in,
                              void* d_out, int out_size)
{
    const float* x     = (const float*)d_in[0];
    const int*   mask  = (const int*)  d_in[1];
    const float* w_qkv = (const float*)d_in[2];
    const float* b_qkv = (const float*)d_in[3];
    const float* w_o   = (const float*)d_in[4];
    const float* b_o   = (const float*)d_in[5];
    float* out = (float*)d_out;

    const int gsmem = (2 * ABUF + 2 * BBUF) * (int)sizeof(uint32_t);  // 30720
    cudaFuncSetAttribute(gemm_tc<0>, cudaFuncAttributeMaxDynamicSharedMemorySize, gsmem);
    cudaFuncSetAttribute(gemm_tc<1>, cudaFuncAttributeMaxDynamicSharedMemorySize, gsmem);

    // 0) pack mask bits
    pack_mask<<<(Sk * 64) / 256, 256>>>(mask);

    // 1) QKV projection + head scatter (TF32 tensor cores; K/V stored fp16)
    gemm_tc<0><<<dim3((3 * Dk) / 64, (Bk * Sk) / 128), 256, gsmem>>>(
        x, w_qkv, b_qkv, nullptr, Bk * Sk, 3 * Dk, Dk);

    // 2) Flash attention (fp16 tensor cores)
    flash_tc<<<dim3(Sk / 64, Bk * Hk), 128>>>();

    // 3) Output projection (TF32 tensor cores)
    gemm_tc<1><<<dim3(Dk / 64, (Bk * Sk) / 128), 256, gsmem>>>(
        x /*ignored*/, w_o, b_o, out, Bk * Sk, Dk, Dk);
}